// round 2
// baseline (speedup 1.0000x reference)
#include <cuda_runtime.h>
#include <math.h>

#define BB 8
#define PP 8192
#define FF 32
#define MM 2048
#define KK 64
#define NPTS (BB*PP)     // 65536
#define NC   (BB*MM)     // 16384
#define R2   0.04f

// ------------ scratch (device globals; no allocation allowed) ------------
__device__ float g_a[NPTS*64];     // per-point layer1 pre-activation (incl. b1 + pos@W1p)
__device__ float g_cent[NC*3];     // centroid coords (bit-exact copies of pos rows)
__device__ int   g_nb[NC*KK];      // neighbor indices (local to cloud)
__device__ int   g_cnt[NC];        // valid neighbor count (<= K)

// =========================================================================
// Kernel 1: farthest point sampling. One block per cloud, 1024 threads,
// 8 points per thread in registers. Exact reference semantics:
// argmax picks max dist, ties -> lowest index. No fma contraction in the
// distance (matches (dx*dx + dy*dy) + dz*dz evaluation).
// =========================================================================
__global__ __launch_bounds__(1024) void fps_kernel(const float* __restrict__ pos,
                                                   float* __restrict__ out_cent)
{
    extern __shared__ float sm[];
    float* sx = sm;
    float* sy = sm + PP;
    float* sz = sm + 2*PP;
    __shared__ unsigned s_wd[32];
    __shared__ unsigned s_wi[32];
    __shared__ int s_sel;

    const int b   = blockIdx.x;
    const int tid = threadIdx.x;
    const int lane = tid & 31;
    const int wid  = tid >> 5;
    const float* pb = pos + (size_t)b * PP * 3;

    float px[8], py[8], pz[8], dist[8];
#pragma unroll
    for (int u = 0; u < 8; u++) {
        int i = u * 1024 + tid;
        float x = pb[i*3+0], y = pb[i*3+1], z = pb[i*3+2];
        px[u] = x; py[u] = y; pz[u] = z;
        sx[i] = x; sy[i] = y; sz[i] = z;
        dist[u] = INFINITY;
    }
    __syncthreads();

    float lx = sx[0], ly = sy[0], lz = sz[0];
    if (tid == 0) {
        int m0 = b * MM;
        g_cent[m0*3+0] = lx; g_cent[m0*3+1] = ly; g_cent[m0*3+2] = lz;
        out_cent[m0*3+0] = lx; out_cent[m0*3+1] = ly; out_cent[m0*3+2] = lz;
    }

    for (int it = 1; it < MM; it++) {
        float bd = -1.0f; int bi = 0;
#pragma unroll
        for (int u = 0; u < 8; u++) {
            float dx = __fsub_rn(px[u], lx);
            float dy = __fsub_rn(py[u], ly);
            float dz = __fsub_rn(pz[u], lz);
            float d  = __fadd_rn(__fadd_rn(__fmul_rn(dx,dx), __fmul_rn(dy,dy)),
                                 __fmul_rn(dz,dz));
            float dd = fminf(dist[u], d);
            dist[u] = dd;
            if (dd > bd) { bd = dd; bi = u * 1024 + tid; }  // u ascending => lowest idx kept
        }
        // warp argmax: max dist, tie -> min global index
        unsigned key  = __float_as_uint(bd);               // bd >= 0 -> bits monotonic
        unsigned wmax = __reduce_max_sync(0xffffffffu, key);
        unsigned cand = (key == wmax) ? (unsigned)bi : 0xffffffffu;
        unsigned widx = __reduce_min_sync(0xffffffffu, cand);
        if (lane == 0) { s_wd[wid] = wmax; s_wi[wid] = widx; }
        __syncthreads();
        if (wid == 0) {
            unsigned dv = s_wd[lane];
            unsigned iv = s_wi[lane];
            unsigned gmax = __reduce_max_sync(0xffffffffu, dv);
            unsigned c2   = (dv == gmax) ? iv : 0xffffffffu;
            unsigned gi   = __reduce_min_sync(0xffffffffu, c2);
            if (lane == 0) s_sel = (int)gi;
        }
        __syncthreads();
        int gi = s_sel;
        lx = sx[gi]; ly = sy[gi]; lz = sz[gi];
        if (tid == 0) {
            int mi = b * MM + it;
            g_cent[mi*3+0] = lx; g_cent[mi*3+1] = ly; g_cent[mi*3+2] = lz;
            out_cent[mi*3+0] = lx; out_cent[mi*3+1] = ly; out_cent[mi*3+2] = lz;
        }
    }
}

// =========================================================================
// Kernel 2: per-point layer-1 pre-activation
//   a[j][o] = b1[o] + sum_f x[j,f]*W1[f,o] + sum_d pos[j,d]*W1[32+d,o]
// =========================================================================
__global__ __launch_bounds__(256) void point_feat_kernel(const float* __restrict__ pos,
                                                         const float* __restrict__ x,
                                                         const float* __restrict__ W1,
                                                         const float* __restrict__ b1)
{
    int t = blockIdx.x * 256 + threadIdx.x;   // NPTS*64 threads total
    int j = t >> 6;
    int o = t & 63;
    const float* xr = x + (size_t)j * FF;
    const float* pr = pos + (size_t)j * 3;
    float acc = b1[o];
#pragma unroll
    for (int f = 0; f < FF; f++)
        acc = fmaf(__ldg(&xr[f]), __ldg(&W1[f*64 + o]), acc);
#pragma unroll
    for (int d = 0; d < 3; d++)
        acc = fmaf(__ldg(&pr[d]), __ldg(&W1[(FF+d)*64 + o]), acc);
    g_a[(size_t)j*64 + o] = acc;
}

// =========================================================================
// Kernel 3: radius ball query, one warp per centroid, lowest indices first,
// early exit once K neighbors found.
// =========================================================================
__global__ __launch_bounds__(256) void ball_kernel(const float* __restrict__ pos)
{
    int w = (blockIdx.x * blockDim.x + threadIdx.x) >> 5;
    int lane = threadIdx.x & 31;
    if (w >= NC) return;
    int b = w >> 11;   // / MM
    const float* pb = pos + (size_t)b * PP * 3;
    float cx = g_cent[w*3+0], cy = g_cent[w*3+1], cz = g_cent[w*3+2];
    int cnt = 0;
    for (int base = 0; base < PP; base += 32) {
        int i = base + lane;
        float dx = __fsub_rn(cx, pb[i*3+0]);
        float dy = __fsub_rn(cy, pb[i*3+1]);
        float dz = __fsub_rn(cz, pb[i*3+2]);
        float d2 = __fadd_rn(__fadd_rn(__fmul_rn(dx,dx), __fmul_rn(dy,dy)),
                             __fmul_rn(dz,dz));
        bool in = (d2 <= R2);
        unsigned msk = __ballot_sync(0xffffffffu, in);
        int slot = cnt + __popc(msk & ((1u << lane) - 1u));
        if (in && slot < KK) g_nb[(size_t)w*KK + slot] = i;
        cnt += __popc(msk);
        if (cnt >= KK) break;
    }
    if (lane == 0) g_cnt[w] = (cnt < KK) ? cnt : KK;
}

// =========================================================================
// Kernel 4: fused gather + 2-layer MLP + masked max.  256 threads per block,
// 8 centroids per block (amortizes smem-resident W2/W3).
//   H1[k] = relu(a[nb_global[k]] - cent@W1p)   (64x64)
//   H2    = relu(H1 @ W2 + b2)                 (64x64)
//   H3    = relu(H2 @ W3 + b3)                 (64x128)
//   out[m]= colmax over valid k of H3
// =========================================================================
#define CPB 8
__global__ __launch_bounds__(256) void mlp_kernel(const float* __restrict__ W1,
                                                  const float* __restrict__ W2,
                                                  const float* __restrict__ b2,
                                                  const float* __restrict__ W3,
                                                  const float* __restrict__ b3,
                                                  float* __restrict__ outF,
                                                  float* __restrict__ outB)
{
    extern __shared__ float smem4[];
    float* W2s = smem4;            // 4096
    float* W3s = W2s + 4096;       // 8192
    float* H1  = W3s + 8192;       // 64*65
    float* H2  = H1  + 64*65;      // 64*65
    float* red = H2  + 64*65;      // 16*132
    __shared__ float cw[64], b2s[64], b3s[128], W1p[192];

    const int tid = threadIdx.x;
    const int tx = tid & 15, ty = tid >> 4;

    for (int i = tid; i < 4096; i += 256) W2s[i] = W2[i];
    for (int i = tid; i < 8192; i += 256) W3s[i] = W3[i];
    if (tid < 64)  b2s[tid] = b2[tid];
    if (tid < 128) b3s[tid] = b3[tid];
    if (tid < 192) W1p[tid] = W1[FF*64 + tid];   // rows 32..34 of W1
    __syncthreads();

    for (int ci = 0; ci < CPB; ci++) {
        const int m = blockIdx.x * CPB + ci;
        const int cnt = g_cnt[m];
        const int ptbase = (m >> 11) * PP;       // cloud id * P : local->global index

        if (tid < 64) {
            float c0 = g_cent[m*3+0], c1 = g_cent[m*3+1], c2 = g_cent[m*3+2];
            cw[tid] = fmaf(c0, W1p[tid], fmaf(c1, W1p[64+tid], c2 * W1p[128+tid]));
        }
        __syncthreads();

        // gather + layer1 elementwise
        {
            int k = tid >> 2, seg = (tid & 3) * 16;
            if (k < cnt) {
                int j = ptbase + g_nb[(size_t)m*KK + k];    // GLOBAL point index
                const float4* src = (const float4*)(g_a + (size_t)j*64 + seg);
#pragma unroll
                for (int q = 0; q < 4; q++) {
                    float4 v = src[q];
                    int o = seg + q*4;
                    H1[k*65+o+0] = fmaxf(v.x - cw[o+0], 0.f);
                    H1[k*65+o+1] = fmaxf(v.y - cw[o+1], 0.f);
                    H1[k*65+o+2] = fmaxf(v.z - cw[o+2], 0.f);
                    H1[k*65+o+3] = fmaxf(v.w - cw[o+3], 0.f);
                }
            } else {
#pragma unroll
                for (int q = 0; q < 16; q++) H1[k*65+seg+q] = 0.f;
            }
        }
        __syncthreads();

        // GEMM1: H2 = relu(H1 @ W2 + b2)   [64x64]
        {
            float acc[4][4];
#pragma unroll
            for (int i = 0; i < 4; i++)
#pragma unroll
                for (int c = 0; c < 4; c++) acc[i][c] = 0.f;
#pragma unroll 8
            for (int j = 0; j < 64; j++) {
                float4 w = *(const float4*)&W2s[j*64 + tx*4];
#pragma unroll
                for (int i = 0; i < 4; i++) {
                    float a = H1[(ty*4+i)*65 + j];
                    acc[i][0] = fmaf(a, w.x, acc[i][0]);
                    acc[i][1] = fmaf(a, w.y, acc[i][1]);
                    acc[i][2] = fmaf(a, w.z, acc[i][2]);
                    acc[i][3] = fmaf(a, w.w, acc[i][3]);
                }
            }
#pragma unroll
            for (int i = 0; i < 4; i++)
#pragma unroll
                for (int c = 0; c < 4; c++)
                    H2[(ty*4+i)*65 + tx*4 + c] = fmaxf(acc[i][c] + b2s[tx*4+c], 0.f);
        }
        __syncthreads();

        // GEMM2: H3 = relu(H2 @ W3 + b3), fused masked column-max
        {
            float acc[4][8];
#pragma unroll
            for (int i = 0; i < 4; i++)
#pragma unroll
                for (int c = 0; c < 8; c++) acc[i][c] = 0.f;
#pragma unroll 4
            for (int j = 0; j < 64; j++) {
                float4 w0 = *(const float4*)&W3s[j*128 + tx*8];
                float4 w1 = *(const float4*)&W3s[j*128 + tx*8 + 4];
#pragma unroll
                for (int i = 0; i < 4; i++) {
                    float a = H2[(ty*4+i)*65 + j];
                    acc[i][0] = fmaf(a, w0.x, acc[i][0]);
                    acc[i][1] = fmaf(a, w0.y, acc[i][1]);
                    acc[i][2] = fmaf(a, w0.z, acc[i][2]);
                    acc[i][3] = fmaf(a, w0.w, acc[i][3]);
                    acc[i][4] = fmaf(a, w1.x, acc[i][4]);
                    acc[i][5] = fmaf(a, w1.y, acc[i][5]);
                    acc[i][6] = fmaf(a, w1.z, acc[i][6]);
                    acc[i][7] = fmaf(a, w1.w, acc[i][7]);
                }
            }
            float pm[8];
#pragma unroll
            for (int c = 0; c < 8; c++) pm[c] = -3.402823466e38f;
#pragma unroll
            for (int i = 0; i < 4; i++) {
                int k = ty*4 + i;
                if (k < cnt) {
#pragma unroll
                    for (int c = 0; c < 8; c++)
                        pm[c] = fmaxf(pm[c], fmaxf(acc[i][c] + b3s[tx*8+c], 0.f));
                }
            }
#pragma unroll
            for (int c = 0; c < 8; c++) red[ty*132 + tx*8 + c] = pm[c];
        }
        __syncthreads();

        if (tid < 128) {
            float mm = -3.402823466e38f;
#pragma unroll
            for (int g = 0; g < 16; g++) mm = fmaxf(mm, red[g*132 + tid]);
            outF[(size_t)m*128 + tid] = mm;
        }
        if (tid == 0) outB[m] = (float)(m >> 11);   // m / M
        __syncthreads();
    }
}

// =========================================================================
extern "C" void kernel_launch(void* const* d_in, const int* in_sizes, int n_in,
                              void* d_out, int out_size)
{
    const float* pos = (const float*)d_in[0];
    // d_in[1] = batch (implicit by layout, unused)
    const float* x   = (const float*)d_in[2];
    const float* W1  = (const float*)d_in[3];
    const float* b1  = (const float*)d_in[4];
    const float* W2  = (const float*)d_in[5];
    const float* b2  = (const float*)d_in[6];
    const float* W3  = (const float*)d_in[7];
    const float* b3  = (const float*)d_in[8];

    float* out      = (float*)d_out;
    float* out_cent = out;                      // [NC,3]
    float* out_feat = out + (size_t)NC*3;       // [NC,128]
    float* out_b    = out + (size_t)NC*3 + (size_t)NC*128;   // [NC]

    cudaFuncSetAttribute(fps_kernel, cudaFuncAttributeMaxDynamicSharedMemorySize, 3*PP*4);
    cudaFuncSetAttribute(mlp_kernel, cudaFuncAttributeMaxDynamicSharedMemorySize,
                         (4096 + 8192 + 64*65 + 64*65 + 16*132) * 4);

    point_feat_kernel<<<(NPTS*64)/256, 256>>>(pos, x, W1, b1);
    fps_kernel<<<BB, 1024, 3*PP*4>>>(pos, out_cent);
    ball_kernel<<<(NC*32)/256, 256>>>(pos);
    mlp_kernel<<<NC/CPB, 256, (4096 + 8192 + 64*65 + 64*65 + 16*132) * 4>>>(
        W1, W2, b2, W3, b3, out_feat, out_b);
}

// round 3
// speedup vs baseline: 1.2760x; 1.2760x over previous
#include <cuda_runtime.h>
#include <math.h>

#define BB 8
#define PP 8192
#define FF 32
#define MM 2048
#define KK 64
#define NPTS (BB*PP)     // 65536
#define NC   (BB*MM)     // 16384
#define R2   0.04f

typedef unsigned long long ull;

// ------------ scratch (device globals; no allocation allowed) ------------
__device__ float g_a[NPTS*64];     // per-point layer1 pre-activation
__device__ float g_cent[NC*3];
__device__ int   g_nb[NC*KK];
__device__ int   g_cnt[NC];

// ---------------- packed f32x2 helpers (sm_103a) ----------------
__device__ __forceinline__ ull pk2(float lo, float hi) {
    ull r; asm("mov.b64 %0, {%1,%2};" : "=l"(r) : "f"(lo), "f"(hi)); return r;
}
__device__ __forceinline__ void upk2(ull v, float& lo, float& hi) {
    asm("mov.b64 {%0,%1}, %2;" : "=f"(lo), "=f"(hi) : "l"(v));
}
__device__ __forceinline__ ull add2(ull a, ull b) {
    ull r; asm("add.rn.f32x2 %0, %1, %2;" : "=l"(r) : "l"(a), "l"(b)); return r;
}
__device__ __forceinline__ ull mul2(ull a, ull b) {
    ull r; asm("mul.rn.f32x2 %0, %1, %2;" : "=l"(r) : "l"(a), "l"(b)); return r;
}
__device__ __forceinline__ void fma2(ull& acc, ull a, ull b) {
    asm("fma.rn.f32x2 %0, %1, %2, %0;" : "+l"(acc) : "l"(a), "l"(b));
}

// =========================================================================
// Kernel 1: FPS. One block per cloud, 1024 threads, 8 pts/thread (4 f32x2
// pairs). Exact reference arithmetic: per-lane IEEE rn packed sub/mul/add
// in (x^2+y^2)+z^2 order. Argmax: max dist, tie -> lowest global index.
// One __syncthreads per iteration (parity double-buffered warp results,
// redundant final reduce in every warp).
// =========================================================================
__global__ __launch_bounds__(1024) void fps_kernel(const float* __restrict__ pos,
                                                   float* __restrict__ out_cent)
{
    extern __shared__ float sm[];
    float* sx = sm;
    float* sy = sm + PP;
    float* sz = sm + 2*PP;
    __shared__ unsigned s_wd[2][32];
    __shared__ unsigned s_wi[2][32];

    const int b   = blockIdx.x;
    const int tid = threadIdx.x;
    const int lane = tid & 31;
    const int wid  = tid >> 5;
    const float* pb = pos + (size_t)b * PP * 3;

    float pxs[8], pys[8], pzs[8], dist[8];
#pragma unroll
    for (int u = 0; u < 8; u++) {
        int i = u * 1024 + tid;
        float x = pb[i*3+0], y = pb[i*3+1], z = pb[i*3+2];
        pxs[u] = x; pys[u] = y; pzs[u] = z;
        sx[i] = x; sy[i] = y; sz[i] = z;
        dist[u] = INFINITY;
    }
    ull px2[4], py2[4], pz2[4];
#pragma unroll
    for (int p = 0; p < 4; p++) {
        px2[p] = pk2(pxs[2*p], pxs[2*p+1]);
        py2[p] = pk2(pys[2*p], pys[2*p+1]);
        pz2[p] = pk2(pzs[2*p], pzs[2*p+1]);
    }
    __syncthreads();

    float lx = sx[0], ly = sy[0], lz = sz[0];
    if (tid == 0) {
        int m0 = b * MM;
        g_cent[m0*3+0] = lx; g_cent[m0*3+1] = ly; g_cent[m0*3+2] = lz;
        out_cent[m0*3+0] = lx; out_cent[m0*3+1] = ly; out_cent[m0*3+2] = lz;
    }

    for (int it = 1; it < MM; it++) {
        const ull nlx2 = pk2(-lx, -lx);
        const ull nly2 = pk2(-ly, -ly);
        const ull nlz2 = pk2(-lz, -lz);
        float bd = -1.0f; int bi = 0;
#pragma unroll
        for (int p = 0; p < 4; p++) {
            ull tx = add2(px2[p], nlx2); tx = mul2(tx, tx);   // rn(dx)^2
            ull ty = add2(py2[p], nly2); ty = mul2(ty, ty);
            ull s  = add2(tx, ty);                            // rn(dx2+dy2)
            ull tz = add2(pz2[p], nlz2); tz = mul2(tz, tz);
            s = add2(s, tz);                                  // + dz2
            float d0, d1; upk2(s, d0, d1);
            float n0 = fminf(dist[2*p],   d0); dist[2*p]   = n0;
            if (n0 > bd) { bd = n0; bi = (2*p)*1024 + tid; }
            float n1 = fminf(dist[2*p+1], d1); dist[2*p+1] = n1;
            if (n1 > bd) { bd = n1; bi = (2*p+1)*1024 + tid; }
        }
        // warp argmax (max dist; tie -> min global index)
        unsigned key  = __float_as_uint(bd);
        unsigned wmax = __reduce_max_sync(0xffffffffu, key);
        unsigned cand = (key == wmax) ? (unsigned)bi : 0xffffffffu;
        unsigned widx = __reduce_min_sync(0xffffffffu, cand);
        int par = it & 1;
        if (lane == 0) { s_wd[par][wid] = wmax; s_wi[par][wid] = widx; }
        __syncthreads();
        // every warp redundantly reduces the 32 warp results
        unsigned dv = s_wd[par][lane];
        unsigned iv = s_wi[par][lane];
        unsigned gmax = __reduce_max_sync(0xffffffffu, dv);
        unsigned c2   = (dv == gmax) ? iv : 0xffffffffu;
        unsigned gi   = __reduce_min_sync(0xffffffffu, c2);
        lx = sx[gi]; ly = sy[gi]; lz = sz[gi];
        if (tid == 0) {
            int mi = b * MM + it;
            g_cent[mi*3+0] = lx; g_cent[mi*3+1] = ly; g_cent[mi*3+2] = lz;
            out_cent[mi*3+0] = lx; out_cent[mi*3+1] = ly; out_cent[mi*3+2] = lz;
        }
    }
}

// =========================================================================
// Kernel 2: per-point layer-1 pre-activation
// =========================================================================
__global__ __launch_bounds__(256) void point_feat_kernel(const float* __restrict__ pos,
                                                         const float* __restrict__ x,
                                                         const float* __restrict__ W1,
                                                         const float* __restrict__ b1)
{
    int t = blockIdx.x * 256 + threadIdx.x;
    int j = t >> 6;
    int o = t & 63;
    const float* xr = x + (size_t)j * FF;
    const float* pr = pos + (size_t)j * 3;
    float acc = b1[o];
#pragma unroll
    for (int f = 0; f < FF; f++)
        acc = fmaf(__ldg(&xr[f]), __ldg(&W1[f*64 + o]), acc);
#pragma unroll
    for (int d = 0; d < 3; d++)
        acc = fmaf(__ldg(&pr[d]), __ldg(&W1[(FF+d)*64 + o]), acc);
    g_a[(size_t)j*64 + o] = acc;
}

// =========================================================================
// Kernel 3: radius ball query (unchanged; proven correct)
// =========================================================================
__global__ __launch_bounds__(256) void ball_kernel(const float* __restrict__ pos)
{
    int w = (blockIdx.x * blockDim.x + threadIdx.x) >> 5;
    int lane = threadIdx.x & 31;
    if (w >= NC) return;
    int b = w >> 11;
    const float* pb = pos + (size_t)b * PP * 3;
    float cx = g_cent[w*3+0], cy = g_cent[w*3+1], cz = g_cent[w*3+2];
    int cnt = 0;
    for (int base = 0; base < PP; base += 32) {
        int i = base + lane;
        float dx = __fsub_rn(cx, pb[i*3+0]);
        float dy = __fsub_rn(cy, pb[i*3+1]);
        float dz = __fsub_rn(cz, pb[i*3+2]);
        float d2 = __fadd_rn(__fadd_rn(__fmul_rn(dx,dx), __fmul_rn(dy,dy)),
                             __fmul_rn(dz,dz));
        bool in = (d2 <= R2);
        unsigned msk = __ballot_sync(0xffffffffu, in);
        int slot = cnt + __popc(msk & ((1u << lane) - 1u));
        if (in && slot < KK) g_nb[(size_t)w*KK + slot] = i;
        cnt += __popc(msk);
        if (cnt >= KK) break;
    }
    if (lane == 0) g_cnt[w] = (cnt < KK) ? cnt : KK;
}

// =========================================================================
// Kernel 4: fused MLP+max. 4 centroids/block (256-row GEMMs), 256 threads,
// 8x8 register tiles, fma.rn.f32x2 packed along the K (reduction) dim.
// Weights pre-transposed in smem to (j-pair, col) float2 layout.
// Thread (tx=tid&7, ty=tid>>3): rows ty*8..+7, cols {2tx+16q+s}.
// =========================================================================
#define H1S (256*66)
__global__ __launch_bounds__(256) void mlp_kernel(const float* __restrict__ W1,
                                                  const float* __restrict__ W2,
                                                  const float* __restrict__ b2,
                                                  const float* __restrict__ W3,
                                                  const float* __restrict__ b3,
                                                  float* __restrict__ outF,
                                                  float* __restrict__ outB)
{
    extern __shared__ float sm4[];
    float* W2p = sm4;              // 4096 floats: [(j2*64+c)*2 + par]
    float* W3p = W2p + 4096;       // 8192 floats: [(j2*128+c)*2 + par]
    float* H1  = W3p + 8192;       // 256 x 66
    float* H2  = H1 + H1S;         // 256 x 66
    float* red = H1;               // reused after GEMM1 (2 halves x 4 ci x 8 g x 64 c)
    __shared__ float cw[256];
    __shared__ float b2s[64], b3s[128];
    __shared__ int cnts[4];

    const int tid = threadIdx.x;
    const int m0 = blockIdx.x * 4;

    for (int i = tid; i < 4096; i += 256) {
        int j = i >> 6, c = i & 63;
        W2p[(((j >> 1) << 6) + c)*2 + (j & 1)] = W2[i];
    }
    for (int i = tid; i < 8192; i += 256) {
        int j = i >> 7, c = i & 127;
        W3p[(((j >> 1) << 7) + c)*2 + (j & 1)] = W3[i];
    }
    if (tid < 64)  b2s[tid] = b2[tid];
    if (tid < 128) b3s[tid] = b3[tid];
    if (tid < 4)   cnts[tid] = g_cnt[m0 + tid];
    {
        int ci = tid >> 6, o = tid & 63;
        float c0 = g_cent[(m0+ci)*3+0], c1 = g_cent[(m0+ci)*3+1], c2v = g_cent[(m0+ci)*3+2];
        cw[tid] = fmaf(c0, __ldg(&W1[2048+o]),
                  fmaf(c1, __ldg(&W1[2112+o]), c2v * __ldg(&W1[2176+o])));
    }
    __syncthreads();

    // ---- gather + layer1 elementwise: one row (neighbor) per thread ----
    {
        int r = tid;
        int ci = r >> 6, k = r & 63;
        int m = m0 + ci;
        float* dst = H1 + r*66;
        if (k < cnts[ci]) {
            int j = ((m >> 11) * PP) + g_nb[(size_t)m*KK + k];
            const float4* src = (const float4*)(g_a + (size_t)j*64);
#pragma unroll
            for (int q = 0; q < 16; q++) {
                float4 v = src[q];
                int o = q*4;
                dst[o+0] = fmaxf(v.x - cw[ci*64+o+0], 0.f);
                dst[o+1] = fmaxf(v.y - cw[ci*64+o+1], 0.f);
                dst[o+2] = fmaxf(v.z - cw[ci*64+o+2], 0.f);
                dst[o+3] = fmaxf(v.w - cw[ci*64+o+3], 0.f);
            }
        } else {
#pragma unroll
            for (int o = 0; o < 64; o++) dst[o] = 0.f;
        }
    }
    __syncthreads();

    const int tx = tid & 7;
    const int ty = tid >> 3;

    // ---- GEMM1: H2 = relu(H1 @ W2 + b2), 256x64, K=64 ----
    {
        ull acc[8][8];
#pragma unroll
        for (int i = 0; i < 8; i++)
#pragma unroll
            for (int c = 0; c < 8; c++) acc[i][c] = 0ull;
#pragma unroll 4
        for (int j2 = 0; j2 < 32; j2++) {
            ull a2[8];
#pragma unroll
            for (int i = 0; i < 8; i++)
                a2[i] = *(const ull*)&H1[(ty*8+i)*66 + 2*j2];
#pragma unroll
            for (int q = 0; q < 4; q++) {
                ulonglong2 w = *(const ulonglong2*)&W2p[((j2 << 6) + 2*tx + 16*q)*2];
#pragma unroll
                for (int i = 0; i < 8; i++) {
                    fma2(acc[i][2*q],   a2[i], w.x);
                    fma2(acc[i][2*q+1], a2[i], w.y);
                }
            }
        }
#pragma unroll
        for (int i = 0; i < 8; i++) {
#pragma unroll
            for (int q = 0; q < 4; q++) {
                int col = 2*tx + 16*q;
                float l0, h0, l1, h1;
                upk2(acc[i][2*q],   l0, h0);
                upk2(acc[i][2*q+1], l1, h1);
                float2 v;
                v.x = fmaxf(l0 + h0 + b2s[col],   0.f);
                v.y = fmaxf(l1 + h1 + b2s[col+1], 0.f);
                *(float2*)&H2[(ty*8+i)*66 + col] = v;
            }
        }
    }
    __syncthreads();

    // ---- GEMM2: H3 = relu(H2 @ W3 + b3), 2 column halves, fused max ----
    const int ci = ty >> 3;
    const int g  = ty & 7;
    const int cnt = cnts[ci];
#pragma unroll 1
    for (int h = 0; h < 2; h++) {
        ull acc[8][8];
#pragma unroll
        for (int i = 0; i < 8; i++)
#pragma unroll
            for (int c = 0; c < 8; c++) acc[i][c] = 0ull;
#pragma unroll 4
        for (int j2 = 0; j2 < 32; j2++) {
            ull a2[8];
#pragma unroll
            for (int i = 0; i < 8; i++)
                a2[i] = *(const ull*)&H2[(ty*8+i)*66 + 2*j2];
#pragma unroll
            for (int q = 0; q < 4; q++) {
                ulonglong2 w = *(const ulonglong2*)&W3p[((j2 << 7) + h*64 + 2*tx + 16*q)*2];
#pragma unroll
                for (int i = 0; i < 8; i++) {
                    fma2(acc[i][2*q],   a2[i], w.x);
                    fma2(acc[i][2*q+1], a2[i], w.y);
                }
            }
        }
        float pm[8];
#pragma unroll
        for (int c = 0; c < 8; c++) pm[c] = -3.402823466e38f;
#pragma unroll
        for (int i = 0; i < 8; i++) {
            int k = g*8 + i;
            if (k < cnt) {
#pragma unroll
                for (int q = 0; q < 4; q++) {
                    int col = 2*tx + 16*q;
                    float l0, h0v, l1, h1v;
                    upk2(acc[i][2*q],   l0, h0v);
                    upk2(acc[i][2*q+1], l1, h1v);
                    pm[2*q]   = fmaxf(pm[2*q],   fmaxf(l0 + h0v + b3s[h*64+col],   0.f));
                    pm[2*q+1] = fmaxf(pm[2*q+1], fmaxf(l1 + h1v + b3s[h*64+col+1], 0.f));
                }
            }
        }
#pragma unroll
        for (int q = 0; q < 4; q++) {
            int col = 2*tx + 16*q;
            float2 v; v.x = pm[2*q]; v.y = pm[2*q+1];
            *(float2*)&red[h*2048 + (ci*8 + g)*64 + col] = v;
        }
    }
    __syncthreads();

    // ---- final reduce over the 8 row-groups, write output ----
    for (int t = tid; t < 512; t += 256) {
        int cci = t >> 7, col = t & 127;
        int h = col >> 6, c64 = col & 63;
        float mm = -3.402823466e38f;
#pragma unroll
        for (int gg = 0; gg < 8; gg++)
            mm = fmaxf(mm, red[h*2048 + (cci*8 + gg)*64 + c64]);
        outF[(size_t)(m0+cci)*128 + col] = mm;
    }
    if (tid < 4) outB[m0 + tid] = (float)((m0 + tid) >> 11);
}

// =========================================================================
extern "C" void kernel_launch(void* const* d_in, const int* in_sizes, int n_in,
                              void* d_out, int out_size)
{
    const float* pos = (const float*)d_in[0];
    const float* x   = (const float*)d_in[2];
    const float* W1  = (const float*)d_in[3];
    const float* b1  = (const float*)d_in[4];
    const float* W2  = (const float*)d_in[5];
    const float* b2  = (const float*)d_in[6];
    const float* W3  = (const float*)d_in[7];
    const float* b3  = (const float*)d_in[8];

    float* out      = (float*)d_out;
    float* out_cent = out;
    float* out_feat = out + (size_t)NC*3;
    float* out_b    = out + (size_t)NC*3 + (size_t)NC*128;

    const int mlp_smem = (4096 + 8192 + H1S + H1S) * 4;
    cudaFuncSetAttribute(fps_kernel, cudaFuncAttributeMaxDynamicSharedMemorySize, 3*PP*4);
    cudaFuncSetAttribute(mlp_kernel, cudaFuncAttributeMaxDynamicSharedMemorySize, mlp_smem);

    point_feat_kernel<<<(NPTS*64)/256, 256>>>(pos, x, W1, b1);
    fps_kernel<<<BB, 1024, 3*PP*4>>>(pos, out_cent);
    ball_kernel<<<(NC*32)/256, 256>>>(pos);
    mlp_kernel<<<NC/4, 256, mlp_smem>>>(W1, W2, b2, W3, b3, out_feat, out_b);
}

// round 6
// speedup vs baseline: 1.3015x; 1.0200x over previous
#include <cuda_runtime.h>
#include <math.h>

#define BB 8
#define PP 8192
#define FF 32
#define MM 2048
#define KK 64
#define NPTS (BB*PP)     // 65536
#define NC   (BB*MM)     // 16384
#define R2   0.04f

typedef unsigned long long ull;

// ------------ scratch (device globals; no allocation allowed) ------------
__device__ float g_a[NPTS*64];     // per-point layer1 pre-activation
__device__ float g_cent[NC*3];
__device__ int   g_nb[NC*KK];
__device__ int   g_cnt[NC];
__device__ float g_W2p[4096];      // W2 transposed to (j-pair, col, par)
__device__ float g_W3p[8192];      // W3 transposed to (j-pair, col, par)

// ---------------- packed f32x2 helpers (sm_103a) ----------------
__device__ __forceinline__ ull pk2(float lo, float hi) {
    ull r; asm("mov.b64 %0, {%1,%2};" : "=l"(r) : "f"(lo), "f"(hi)); return r;
}
__device__ __forceinline__ void upk2(ull v, float& lo, float& hi) {
    asm("mov.b64 {%0,%1}, %2;" : "=f"(lo), "=f"(hi) : "l"(v));
}
__device__ __forceinline__ ull add2(ull a, ull b) {
    ull r; asm("add.rn.f32x2 %0, %1, %2;" : "=l"(r) : "l"(a), "l"(b)); return r;
}
__device__ __forceinline__ ull mul2(ull a, ull b) {
    ull r; asm("mul.rn.f32x2 %0, %1, %2;" : "=l"(r) : "l"(a), "l"(b)); return r;
}
__device__ __forceinline__ void fma2(ull& acc, ull a, ull b) {
    asm("fma.rn.f32x2 %0, %1, %2, %0;" : "+l"(acc) : "l"(a), "l"(b));
}

// =========================================================================
// Kernel 1: FPS. One block per cloud, 1024 threads, 8 pts/thread. Packed
// exact rn arithmetic for the distance (add2/mul2, per-lane IEEE rn in
// (x^2+y^2)+z^2 order); scalar fminf for the dist cascade; per-thread max
// via fmaxf log-tree; index recovered post-hoc by descending equality scan
// (-> lowest global index on ties), then warp/block REDUX.
// =========================================================================
__global__ __launch_bounds__(1024) void fps_kernel(const float* __restrict__ pos,
                                                   float* __restrict__ out_cent)
{
    extern __shared__ float sm[];
    float* sx = sm;
    float* sy = sm + PP;
    float* sz = sm + 2*PP;
    __shared__ unsigned s_wd[2][32];
    __shared__ unsigned s_wi[2][32];

    const int b   = blockIdx.x;
    const int tid = threadIdx.x;
    const int lane = tid & 31;
    const int wid  = tid >> 5;
    const float* pb = pos + (size_t)b * PP * 3;

    float pxs[8], pys[8], pzs[8], dist[8];
#pragma unroll
    for (int u = 0; u < 8; u++) {
        int i = u * 1024 + tid;
        float x = pb[i*3+0], y = pb[i*3+1], z = pb[i*3+2];
        pxs[u] = x; pys[u] = y; pzs[u] = z;
        sx[i] = x; sy[i] = y; sz[i] = z;
        dist[u] = INFINITY;
    }
    ull px2[4], py2[4], pz2[4];
#pragma unroll
    for (int p = 0; p < 4; p++) {
        px2[p] = pk2(pxs[2*p], pxs[2*p+1]);
        py2[p] = pk2(pys[2*p], pys[2*p+1]);
        pz2[p] = pk2(pzs[2*p], pzs[2*p+1]);
    }
    __syncthreads();

    float lx = sx[0], ly = sy[0], lz = sz[0];
    if (tid == 0) {
        int m0 = b * MM;
        g_cent[m0*3+0] = lx; g_cent[m0*3+1] = ly; g_cent[m0*3+2] = lz;
        out_cent[m0*3+0] = lx; out_cent[m0*3+1] = ly; out_cent[m0*3+2] = lz;
    }

    for (int it = 1; it < MM; it++) {
        const ull nlx2 = pk2(-lx, -lx);
        const ull nly2 = pk2(-ly, -ly);
        const ull nlz2 = pk2(-lz, -lz);
#pragma unroll
        for (int p = 0; p < 4; p++) {
            ull tx = add2(px2[p], nlx2); tx = mul2(tx, tx);   // rn(dx)^2
            ull ty = add2(py2[p], nly2); ty = mul2(ty, ty);
            ull s  = add2(tx, ty);                            // rn(dx2+dy2)
            ull tz = add2(pz2[p], nlz2); tz = mul2(tz, tz);
            s = add2(s, tz);                                  // + dz2
            float d0, d1; upk2(s, d0, d1);
            dist[2*p]   = fminf(dist[2*p],   d0);
            dist[2*p+1] = fminf(dist[2*p+1], d1);
        }
        // per-thread max via log-tree (no serial SEL chain)
        float m0v = fmaxf(dist[0], dist[1]);
        float m1v = fmaxf(dist[2], dist[3]);
        float m2v = fmaxf(dist[4], dist[5]);
        float m3v = fmaxf(dist[6], dist[7]);
        float m01 = fmaxf(m0v, m1v);
        float m23 = fmaxf(m2v, m3v);
        float bd  = fmaxf(m01, m23);
        unsigned key  = __float_as_uint(bd);          // dists >= 0: bits monotonic
        unsigned wmax = __reduce_max_sync(0xffffffffu, key);
        // recover lowest matching global index (descending scan -> lowest wins)
        float gm = __uint_as_float(wmax);
        unsigned cand = 0xffffffffu;
#pragma unroll
        for (int u = 7; u >= 0; u--)
            if (dist[u] == gm) cand = (unsigned)(u*1024 + tid);
        unsigned widx = __reduce_min_sync(0xffffffffu, cand);
        int par = it & 1;
        if (lane == 0) { s_wd[par][wid] = wmax; s_wi[par][wid] = widx; }
        __syncthreads();
        unsigned dv = s_wd[par][lane];
        unsigned iv = s_wi[par][lane];
        unsigned gmax = __reduce_max_sync(0xffffffffu, dv);
        unsigned c2   = (dv == gmax) ? iv : 0xffffffffu;
        unsigned gi   = __reduce_min_sync(0xffffffffu, c2);
        lx = sx[gi]; ly = sy[gi]; lz = sz[gi];
        if (tid == 0) {
            int mi = b * MM + it;
            g_cent[mi*3+0] = lx; g_cent[mi*3+1] = ly; g_cent[mi*3+2] = lz;
            out_cent[mi*3+0] = lx; out_cent[mi*3+1] = ly; out_cent[mi*3+2] = lz;
        }
    }
}

// =========================================================================
// Kernel 2: per-point layer-1 pre-activation
// =========================================================================
__global__ __launch_bounds__(256) void point_feat_kernel(const float* __restrict__ pos,
                                                         const float* __restrict__ x,
                                                         const float* __restrict__ W1,
                                                         const float* __restrict__ b1)
{
    int t = blockIdx.x * 256 + threadIdx.x;
    int j = t >> 6;
    int o = t & 63;
    const float* xr = x + (size_t)j * FF;
    const float* pr = pos + (size_t)j * 3;
    float acc = b1[o];
#pragma unroll
    for (int f = 0; f < FF; f++)
        acc = fmaf(__ldg(&xr[f]), __ldg(&W1[f*64 + o]), acc);
#pragma unroll
    for (int d = 0; d < 3; d++)
        acc = fmaf(__ldg(&pr[d]), __ldg(&W1[(FF+d)*64 + o]), acc);
    g_a[(size_t)j*64 + o] = acc;
}

// =========================================================================
// Kernel 2b: weight transpose into (j-pair, col, parity) layout
// =========================================================================
__global__ __launch_bounds__(256) void wprep_kernel(const float* __restrict__ W2,
                                                    const float* __restrict__ W3)
{
    int t = blockIdx.x * 256 + threadIdx.x;
    if (t < 4096) {
        int j = t >> 6, c = t & 63;
        g_W2p[(((j >> 1) << 6) + c)*2 + (j & 1)] = W2[t];
    }
    if (t < 8192) {
        int j = t >> 7, c = t & 127;
        g_W3p[(((j >> 1) << 7) + c)*2 + (j & 1)] = W3[t];
    }
}

// =========================================================================
// Kernel 3: radius ball query (unchanged; proven correct)
// =========================================================================
__global__ __launch_bounds__(256) void ball_kernel(const float* __restrict__ pos)
{
    int w = (blockIdx.x * blockDim.x + threadIdx.x) >> 5;
    int lane = threadIdx.x & 31;
    if (w >= NC) return;
    int b = w >> 11;
    const float* pb = pos + (size_t)b * PP * 3;
    float cx = g_cent[w*3+0], cy = g_cent[w*3+1], cz = g_cent[w*3+2];
    int cnt = 0;
    for (int base = 0; base < PP; base += 32) {
        int i = base + lane;
        float dx = __fsub_rn(cx, pb[i*3+0]);
        float dy = __fsub_rn(cy, pb[i*3+1]);
        float dz = __fsub_rn(cz, pb[i*3+2]);
        float d2 = __fadd_rn(__fadd_rn(__fmul_rn(dx,dx), __fmul_rn(dy,dy)),
                             __fmul_rn(dz,dz));
        bool in = (d2 <= R2);
        unsigned msk = __ballot_sync(0xffffffffu, in);
        int slot = cnt + __popc(msk & ((1u << lane) - 1u));
        if (in && slot < KK) g_nb[(size_t)w*KK + slot] = i;
        cnt += __popc(msk);
        if (cnt >= KK) break;
    }
    if (lane == 0) g_cnt[w] = (cnt < KK) ? cnt : KK;
}

// =========================================================================
// Kernel 4: fused MLP+max. 2 centroids/block (128-row GEMMs), 256 threads,
// 2 CTAs/SM (67.6KB smem). Weights read from g_W2p/g_W3p via L1 (coalesced
// + broadcast). 4x8 register tiles, fma.rn.f32x2 packed along K.
// =========================================================================
__global__ __launch_bounds__(256, 2) void mlp_kernel(const float* __restrict__ W1,
                                                     const float* __restrict__ b2,
                                                     const float* __restrict__ b3,
                                                     float* __restrict__ outF,
                                                     float* __restrict__ outB)
{
    extern __shared__ float sm4[];
    float* H1  = sm4;              // 128 x 66
    float* H2  = H1 + 128*66;      // 128 x 66
    float* red = H1;               // reused after GEMM1-read (4*16*64 = 4096)
    __shared__ float cw[128];
    __shared__ int cnts[2];

    const int tid = threadIdx.x;
    const int m0 = blockIdx.x * 2;

    if (tid < 2) cnts[tid] = g_cnt[m0 + tid];
    if (tid < 128) {
        int ci = tid >> 6, o = tid & 63;
        float c0 = g_cent[(m0+ci)*3+0], c1 = g_cent[(m0+ci)*3+1], c2v = g_cent[(m0+ci)*3+2];
        cw[tid] = fmaf(c0, __ldg(&W1[2048+o]),
                  fmaf(c1, __ldg(&W1[2112+o]), c2v * __ldg(&W1[2176+o])));
    }
    __syncthreads();

    // ---- gather + layer1 elementwise: half a row per thread ----
    {
        int r = tid >> 1;                  // 0..127
        int seg = (tid & 1) * 32;
        int ci = r >> 6, k = r & 63;
        int m = m0 + ci;
        float* dst = H1 + r*66 + seg;
        if (k < cnts[ci]) {
            int j = ((m >> 11) * PP) + g_nb[(size_t)m*KK + k];
            const float4* src = (const float4*)(g_a + (size_t)j*64 + seg);
#pragma unroll
            for (int q = 0; q < 8; q++) {
                float4 v = src[q];
                int o = seg + q*4;
                dst[q*4+0] = fmaxf(v.x - cw[ci*64+o+0], 0.f);
                dst[q*4+1] = fmaxf(v.y - cw[ci*64+o+1], 0.f);
                dst[q*4+2] = fmaxf(v.z - cw[ci*64+o+2], 0.f);
                dst[q*4+3] = fmaxf(v.w - cw[ci*64+o+3], 0.f);
            }
        } else {
#pragma unroll
            for (int q = 0; q < 32; q++) dst[q] = 0.f;
        }
    }
    __syncthreads();

    const int tx = tid & 7;
    const int ty = tid >> 3;              // 0..31, rows 4ty..4ty+3

    // ---- GEMM1: H2 = relu(H1 @ W2 + b2), 128x64, K=64 ----
    {
        ull acc[4][8];
#pragma unroll
        for (int i = 0; i < 4; i++)
#pragma unroll
            for (int c = 0; c < 8; c++) acc[i][c] = 0ull;
#pragma unroll 4
        for (int j2 = 0; j2 < 32; j2++) {
            ull a2[4];
#pragma unroll
            for (int i = 0; i < 4; i++)
                a2[i] = *(const ull*)&H1[(ty*4+i)*66 + 2*j2];
#pragma unroll
            for (int q = 0; q < 4; q++) {
                ulonglong2 w = __ldg((const ulonglong2*)&g_W2p[((j2 << 6) + 2*tx + 16*q)*2]);
#pragma unroll
                for (int i = 0; i < 4; i++) {
                    fma2(acc[i][2*q],   a2[i], w.x);
                    fma2(acc[i][2*q+1], a2[i], w.y);
                }
            }
        }
#pragma unroll
        for (int i = 0; i < 4; i++) {
#pragma unroll
            for (int q = 0; q < 4; q++) {
                int col = 2*tx + 16*q;
                float l0, h0, l1, h1;
                upk2(acc[i][2*q],   l0, h0);
                upk2(acc[i][2*q+1], l1, h1);
                float2 v;
                v.x = fmaxf(l0 + h0 + __ldg(&b2[col]),   0.f);
                v.y = fmaxf(l1 + h1 + __ldg(&b2[col+1]), 0.f);
                *(float2*)&H2[(ty*4+i)*66 + col] = v;
            }
        }
    }
    __syncthreads();

    // ---- GEMM2: H3 = relu(H2 @ W3 + b3), 2 column halves, fused max ----
    const int ci = ty >> 4;               // 0..1
    const int g  = ty & 15;               // row group within centroid
    const int cnt = cnts[ci];
#pragma unroll 1
    for (int h = 0; h < 2; h++) {
        ull acc[4][8];
#pragma unroll
        for (int i = 0; i < 4; i++)
#pragma unroll
            for (int c = 0; c < 8; c++) acc[i][c] = 0ull;
#pragma unroll 4
        for (int j2 = 0; j2 < 32; j2++) {
            ull a2[4];
#pragma unroll
            for (int i = 0; i < 4; i++)
                a2[i] = *(const ull*)&H2[(ty*4+i)*66 + 2*j2];
#pragma unroll
            for (int q = 0; q < 4; q++) {
                ulonglong2 w = __ldg((const ulonglong2*)&g_W3p[((j2 << 7) + h*64 + 2*tx + 16*q)*2]);
#pragma unroll
                for (int i = 0; i < 4; i++) {
                    fma2(acc[i][2*q],   a2[i], w.x);
                    fma2(acc[i][2*q+1], a2[i], w.y);
                }
            }
        }
        float pm[8];
#pragma unroll
        for (int c = 0; c < 8; c++) pm[c] = -3.402823466e38f;
#pragma unroll
        for (int i = 0; i < 4; i++) {
            int k = g*4 + i;
            if (k < cnt) {
#pragma unroll
                for (int q = 0; q < 4; q++) {
                    int col = 2*tx + 16*q;
                    float l0, h0v, l1, h1v;
                    upk2(acc[i][2*q],   l0, h0v);
                    upk2(acc[i][2*q+1], l1, h1v);
                    pm[2*q]   = fmaxf(pm[2*q],   fmaxf(l0 + h0v + __ldg(&b3[h*64+col]),   0.f));
                    pm[2*q+1] = fmaxf(pm[2*q+1], fmaxf(l1 + h1v + __ldg(&b3[h*64+col+1]), 0.f));
                }
            }
        }
#pragma unroll
        for (int q = 0; q < 4; q++) {
            int col = 2*tx + 16*q;
            float2 v; v.x = pm[2*q]; v.y = pm[2*q+1];
            *(float2*)&red[((h*2 + ci)*16 + g)*64 + col] = v;
        }
    }
    __syncthreads();

    // ---- final reduce over the 16 row-groups, write output ----
    {
        int cci = tid >> 7, col = tid & 127;
        int h = col >> 6, c64 = col & 63;
        float mmv = -3.402823466e38f;
#pragma unroll
        for (int gg = 0; gg < 16; gg++)
            mmv = fmaxf(mmv, red[((h*2 + cci)*16 + gg)*64 + c64]);
        outF[(size_t)(m0+cci)*128 + col] = mmv;
    }
    if (tid < 2) outB[m0 + tid] = (float)((m0 + tid) >> 11);
}

// =========================================================================
extern "C" void kernel_launch(void* const* d_in, const int* in_sizes, int n_in,
                              void* d_out, int out_size)
{
    const float* pos = (const float*)d_in[0];
    const float* x   = (const float*)d_in[2];
    const float* W1  = (const float*)d_in[3];
    const float* b1  = (const float*)d_in[4];
    const float* W2  = (const float*)d_in[5];
    const float* b2  = (const float*)d_in[6];
    const float* W3  = (const float*)d_in[7];
    const float* b3  = (const float*)d_in[8];

    float* out      = (float*)d_out;
    float* out_cent = out;
    float* out_feat = out + (size_t)NC*3;
    float* out_b    = out + (size_t)NC*3 + (size_t)NC*128;

    const int mlp_smem = (2*128*66) * 4;   // 67584 B
    cudaFuncSetAttribute(fps_kernel, cudaFuncAttributeMaxDynamicSharedMemorySize, 3*PP*4);
    cudaFuncSetAttribute(mlp_kernel, cudaFuncAttributeMaxDynamicSharedMemorySize, mlp_smem);

    point_feat_kernel<<<(NPTS*64)/256, 256>>>(pos, x, W1, b1);
    wprep_kernel<<<32, 256>>>(W2, W3);
    fps_kernel<<<BB, 1024, 3*PP*4>>>(pos, out_cent);
    ball_kernel<<<(NC*32)/256, 256>>>(pos);
    mlp_kernel<<<NC/2, 256, mlp_smem>>>(W1, b2, b3, out_feat, out_b);
}

// round 8
// speedup vs baseline: 1.4280x; 1.0972x over previous
#include <cuda_runtime.h>
#include <math.h>

#define BB 8
#define PP 8192
#define FF 32
#define MM 2048
#define KK 64
#define NPTS (BB*PP)     // 65536
#define NC   (BB*MM)     // 16384
#define R2   0.04f

typedef unsigned long long ull;

// ------------ scratch (device globals; no allocation allowed) ------------
__device__ float g_a[NPTS*64];     // per-point layer1 pre-activation
__device__ float g_cent[NC*3];
__device__ int   g_nb[NC*KK];
__device__ int   g_cnt[NC];
__device__ float g_W2p[4096];      // W2 transposed to (j-pair, col, par)
__device__ float g_W3p[8192];      // W3 transposed to (j-pair, col, par)

// ---------------- packed f32x2 helpers (sm_103a) ----------------
__device__ __forceinline__ ull pk2(float lo, float hi) {
    ull r; asm("mov.b64 %0, {%1,%2};" : "=l"(r) : "f"(lo), "f"(hi)); return r;
}
__device__ __forceinline__ void upk2(ull v, float& lo, float& hi) {
    asm("mov.b64 {%0,%1}, %2;" : "=f"(lo), "=f"(hi) : "l"(v));
}
__device__ __forceinline__ ull add2(ull a, ull b) {
    ull r; asm("add.rn.f32x2 %0, %1, %2;" : "=l"(r) : "l"(a), "l"(b)); return r;
}
__device__ __forceinline__ ull mul2(ull a, ull b) {
    ull r; asm("mul.rn.f32x2 %0, %1, %2;" : "=l"(r) : "l"(a), "l"(b)); return r;
}
__device__ __forceinline__ void fma2(ull& acc, ull a, ull b) {
    asm("fma.rn.f32x2 %0, %1, %2, %0;" : "+l"(acc) : "l"(a), "l"(b));
}

// =========================================================================
// Kernel 1: FPS. One block per cloud, 1024 threads, 8 pts/thread. Packed
// exact rn distance arithmetic ((x^2+y^2)+z^2 order), scalar fminf cascade,
// fmaxf log-tree per-thread max. Global winner: warp REDUX -> smem ->
// all-warp REDUX of 32 warp maxes; only threads matching the global max
// scan their dists and atomicMin the lowest global index (exact reference
// tie-break; deterministic). Parity-tagged result slot, reset 1 iter ahead.
// =========================================================================
__global__ __launch_bounds__(1024) void fps_kernel(const float* __restrict__ pos,
                                                   float* __restrict__ out_cent)
{
    extern __shared__ float sm[];
    float* sx = sm;
    float* sy = sm + PP;
    float* sz = sm + 2*PP;
    __shared__ unsigned s_wd[2][32];
    __shared__ unsigned s_sel[2];

    const int b   = blockIdx.x;
    const int tid = threadIdx.x;
    const int lane = tid & 31;
    const int wid  = tid >> 5;
    const float* pb = pos + (size_t)b * PP * 3;

    float pxs[8], pys[8], pzs[8], dist[8];
#pragma unroll
    for (int u = 0; u < 8; u++) {
        int i = u * 1024 + tid;
        float x = pb[i*3+0], y = pb[i*3+1], z = pb[i*3+2];
        pxs[u] = x; pys[u] = y; pzs[u] = z;
        sx[i] = x; sy[i] = y; sz[i] = z;
        dist[u] = INFINITY;
    }
    ull px2[4], py2[4], pz2[4];
#pragma unroll
    for (int p = 0; p < 4; p++) {
        px2[p] = pk2(pxs[2*p], pxs[2*p+1]);
        py2[p] = pk2(pys[2*p], pys[2*p+1]);
        pz2[p] = pk2(pzs[2*p], pzs[2*p+1]);
    }
    if (tid < 2) s_sel[tid] = 0xffffffffu;
    __syncthreads();

    float lx = sx[0], ly = sy[0], lz = sz[0];
    if (tid == 0) {
        int m0 = b * MM;
        g_cent[m0*3+0] = lx; g_cent[m0*3+1] = ly; g_cent[m0*3+2] = lz;
        out_cent[m0*3+0] = lx; out_cent[m0*3+1] = ly; out_cent[m0*3+2] = lz;
    }

    for (int it = 1; it < MM; it++) {
        const int par = it & 1;
        const ull nlx2 = pk2(-lx, -lx);
        const ull nly2 = pk2(-ly, -ly);
        const ull nlz2 = pk2(-lz, -lz);
#pragma unroll
        for (int p = 0; p < 4; p++) {
            ull tx = add2(px2[p], nlx2); tx = mul2(tx, tx);   // rn(dx)^2
            ull ty = add2(py2[p], nly2); ty = mul2(ty, ty);
            ull s  = add2(tx, ty);                            // rn(dx2+dy2)
            ull tz = add2(pz2[p], nlz2); tz = mul2(tz, tz);
            s = add2(s, tz);                                  // + dz2
            float d0, d1; upk2(s, d0, d1);
            dist[2*p]   = fminf(dist[2*p],   d0);
            dist[2*p+1] = fminf(dist[2*p+1], d1);
        }
        // per-thread max via log-tree
        float m0v = fmaxf(dist[0], dist[1]);
        float m1v = fmaxf(dist[2], dist[3]);
        float m2v = fmaxf(dist[4], dist[5]);
        float m3v = fmaxf(dist[6], dist[7]);
        float bd  = fmaxf(fmaxf(m0v, m1v), fmaxf(m2v, m3v));
        unsigned key  = __float_as_uint(bd);          // dists >= 0: bits monotonic
        unsigned wmax = __reduce_max_sync(0xffffffffu, key);
        if (lane == 0) s_wd[par][wid] = wmax;
        __syncthreads();
        // all warps compute the block max over the 32 warp maxes
        unsigned gbits = __reduce_max_sync(0xffffffffu, s_wd[par][lane]);
        if (tid == 0) s_sel[1 - par] = 0xffffffffu;   // reset slot for NEXT iter
        if (key == gbits) {                           // rare: usually one thread
            float gm = __uint_as_float(gbits);
            unsigned cand = 0xffffffffu;
#pragma unroll
            for (int u = 7; u >= 0; u--)
                if (dist[u] == gm) cand = (unsigned)(u*1024 + tid);
            atomicMin(&s_sel[par], cand);
        }
        __syncthreads();
        unsigned gi = s_sel[par];
        lx = sx[gi]; ly = sy[gi]; lz = sz[gi];
        if (tid == 0) {
            int mi = b * MM + it;
            g_cent[mi*3+0] = lx; g_cent[mi*3+1] = ly; g_cent[mi*3+2] = lz;
            out_cent[mi*3+0] = lx; out_cent[mi*3+1] = ly; out_cent[mi*3+2] = lz;
        }
    }
}

// =========================================================================
// Kernel 2: per-point layer-1 pre-activation
// =========================================================================
__global__ __launch_bounds__(256) void point_feat_kernel(const float* __restrict__ pos,
                                                         const float* __restrict__ x,
                                                         const float* __restrict__ W1,
                                                         const float* __restrict__ b1)
{
    int t = blockIdx.x * 256 + threadIdx.x;
    int j = t >> 6;
    int o = t & 63;
    const float* xr = x + (size_t)j * FF;
    const float* pr = pos + (size_t)j * 3;
    float acc = b1[o];
#pragma unroll
    for (int f = 0; f < FF; f++)
        acc = fmaf(__ldg(&xr[f]), __ldg(&W1[f*64 + o]), acc);
#pragma unroll
    for (int d = 0; d < 3; d++)
        acc = fmaf(__ldg(&pr[d]), __ldg(&W1[(FF+d)*64 + o]), acc);
    g_a[(size_t)j*64 + o] = acc;
}

// =========================================================================
// Kernel 2b: weight transpose into (j-pair, col, parity) layout
// =========================================================================
__global__ __launch_bounds__(256) void wprep_kernel(const float* __restrict__ W2,
                                                    const float* __restrict__ W3)
{
    int t = blockIdx.x * 256 + threadIdx.x;
    if (t < 4096) {
        int j = t >> 6, c = t & 63;
        g_W2p[(((j >> 1) << 6) + c)*2 + (j & 1)] = W2[t];
    }
    if (t < 8192) {
        int j = t >> 7, c = t & 127;
        g_W3p[(((j >> 1) << 7) + c)*2 + (j & 1)] = W3[t];
    }
}

// =========================================================================
// Kernel 3: radius ball query. One warp per centroid, 64 points per
// iteration (2 per lane, packed f32x2 distances, per-lane rounding
// identical to scalar). Two ordered ballot+append rounds preserve
// lowest-index-first; early exit at K.
// =========================================================================
__global__ __launch_bounds__(256) void ball_kernel(const float* __restrict__ pos)
{
    int w = (blockIdx.x * blockDim.x + threadIdx.x) >> 5;
    int lane = threadIdx.x & 31;
    if (w >= NC) return;
    int b = w >> 11;
    const float* pb = pos + (size_t)b * PP * 3;
    float cx = g_cent[w*3+0], cy = g_cent[w*3+1], cz = g_cent[w*3+2];
    const ull ncx2 = pk2(-cx, -cx);
    const ull ncy2 = pk2(-cy, -cy);
    const ull ncz2 = pk2(-cz, -cz);
    const unsigned lt = (1u << lane) - 1u;
    int cnt = 0;
    for (int base = 0; base < PP; base += 64) {
        int i0 = base + lane;
        int i1 = i0 + 32;
        float x0 = pb[i0*3+0], y0 = pb[i0*3+1], z0 = pb[i0*3+2];
        float x1 = pb[i1*3+0], y1 = pb[i1*3+1], z1 = pb[i1*3+2];
        ull tx = add2(pk2(x0, x1), ncx2); tx = mul2(tx, tx);  // (p-c)^2 == (c-p)^2
        ull ty = add2(pk2(y0, y1), ncy2); ty = mul2(ty, ty);
        ull s  = add2(tx, ty);
        ull tz = add2(pk2(z0, z1), ncz2); tz = mul2(tz, tz);
        s = add2(s, tz);
        float d0, d1; upk2(s, d0, d1);
        bool in0 = (d0 <= R2);
        bool in1 = (d1 <= R2);
        unsigned m0 = __ballot_sync(0xffffffffu, in0);
        int slot0 = cnt + __popc(m0 & lt);
        if (in0 && slot0 < KK) g_nb[(size_t)w*KK + slot0] = i0;
        cnt += __popc(m0);
        unsigned m1 = __ballot_sync(0xffffffffu, in1);
        int slot1 = cnt + __popc(m1 & lt);
        if (in1 && slot1 < KK) g_nb[(size_t)w*KK + slot1] = i1;
        cnt += __popc(m1);
        if (cnt >= KK) break;
    }
    if (lane == 0) g_cnt[w] = (cnt < KK) ? cnt : KK;
}

// =========================================================================
// Kernel 4: fused MLP+max. 2 centroids/block (128-row GEMMs), 256 threads,
// 2 CTAs/SM (67.6KB smem). Weights read from g_W2p/g_W3p via L1 (coalesced
// + broadcast). 4x8 register tiles, fma.rn.f32x2 packed along K.
// =========================================================================
__global__ __launch_bounds__(256, 2) void mlp_kernel(const float* __restrict__ W1,
                                                     const float* __restrict__ b2,
                                                     const float* __restrict__ b3,
                                                     float* __restrict__ outF,
                                                     float* __restrict__ outB)
{
    extern __shared__ float sm4[];
    float* H1  = sm4;              // 128 x 66
    float* H2  = H1 + 128*66;      // 128 x 66
    float* red = H1;               // reused after GEMM1-read (4*16*64 = 4096)
    __shared__ float cw[128];
    __shared__ int cnts[2];

    const int tid = threadIdx.x;
    const int m0 = blockIdx.x * 2;

    if (tid < 2) cnts[tid] = g_cnt[m0 + tid];
    if (tid < 128) {
        int ci = tid >> 6, o = tid & 63;
        float c0 = g_cent[(m0+ci)*3+0], c1 = g_cent[(m0+ci)*3+1], c2v = g_cent[(m0+ci)*3+2];
        cw[tid] = fmaf(c0, __ldg(&W1[2048+o]),
                  fmaf(c1, __ldg(&W1[2112+o]), c2v * __ldg(&W1[2176+o])));
    }
    __syncthreads();

    // ---- gather + layer1 elementwise: half a row per thread ----
    {
        int r = tid >> 1;                  // 0..127
        int seg = (tid & 1) * 32;
        int ci = r >> 6, k = r & 63;
        int m = m0 + ci;
        float* dst = H1 + r*66 + seg;
        if (k < cnts[ci]) {
            int j = ((m >> 11) * PP) + g_nb[(size_t)m*KK + k];
            const float4* src = (const float4*)(g_a + (size_t)j*64 + seg);
#pragma unroll
            for (int q = 0; q < 8; q++) {
                float4 v = src[q];
                int o = seg + q*4;
                dst[q*4+0] = fmaxf(v.x - cw[ci*64+o+0], 0.f);
                dst[q*4+1] = fmaxf(v.y - cw[ci*64+o+1], 0.f);
                dst[q*4+2] = fmaxf(v.z - cw[ci*64+o+2], 0.f);
                dst[q*4+3] = fmaxf(v.w - cw[ci*64+o+3], 0.f);
            }
        } else {
#pragma unroll
            for (int q = 0; q < 32; q++) dst[q] = 0.f;
        }
    }
    __syncthreads();

    const int tx = tid & 7;
    const int ty = tid >> 3;              // 0..31, rows 4ty..4ty+3

    // ---- GEMM1: H2 = relu(H1 @ W2 + b2), 128x64, K=64 ----
    {
        ull acc[4][8];
#pragma unroll
        for (int i = 0; i < 4; i++)
#pragma unroll
            for (int c = 0; c < 8; c++) acc[i][c] = 0ull;
#pragma unroll 4
        for (int j2 = 0; j2 < 32; j2++) {
            ull a2[4];
#pragma unroll
            for (int i = 0; i < 4; i++)
                a2[i] = *(const ull*)&H1[(ty*4+i)*66 + 2*j2];
#pragma unroll
            for (int q = 0; q < 4; q++) {
                ulonglong2 w = __ldg((const ulonglong2*)&g_W2p[((j2 << 6) + 2*tx + 16*q)*2]);
#pragma unroll
                for (int i = 0; i < 4; i++) {
                    fma2(acc[i][2*q],   a2[i], w.x);
                    fma2(acc[i][2*q+1], a2[i], w.y);
                }
            }
        }
#pragma unroll
        for (int i = 0; i < 4; i++) {
#pragma unroll
            for (int q = 0; q < 4; q++) {
                int col = 2*tx + 16*q;
                float l0, h0, l1, h1;
                upk2(acc[i][2*q],   l0, h0);
                upk2(acc[i][2*q+1], l1, h1);
                float2 v;
                v.x = fmaxf(l0 + h0 + __ldg(&b2[col]),   0.f);
                v.y = fmaxf(l1 + h1 + __ldg(&b2[col+1]), 0.f);
                *(float2*)&H2[(ty*4+i)*66 + col] = v;
            }
        }
    }
    __syncthreads();

    // ---- GEMM2: H3 = relu(H2 @ W3 + b3), 2 column halves, fused max ----
    const int ci = ty >> 4;               // 0..1
    const int g  = ty & 15;               // row group within centroid
    const int cnt = cnts[ci];
#pragma unroll 1
    for (int h = 0; h < 2; h++) {
        ull acc[4][8];
#pragma unroll
        for (int i = 0; i < 4; i++)
#pragma unroll
            for (int c = 0; c < 8; c++) acc[i][c] = 0ull;
#pragma unroll 4
        for (int j2 = 0; j2 < 32; j2++) {
            ull a2[4];
#pragma unroll
            for (int i = 0; i < 4; i++)
                a2[i] = *(const ull*)&H2[(ty*4+i)*66 + 2*j2];
#pragma unroll
            for (int q = 0; q < 4; q++) {
                ulonglong2 w = __ldg((const ulonglong2*)&g_W3p[((j2 << 7) + h*64 + 2*tx + 16*q)*2]);
#pragma unroll
                for (int i = 0; i < 4; i++) {
                    fma2(acc[i][2*q],   a2[i], w.x);
                    fma2(acc[i][2*q+1], a2[i], w.y);
                }
            }
        }
        float pm[8];
#pragma unroll
        for (int c = 0; c < 8; c++) pm[c] = -3.402823466e38f;
#pragma unroll
        for (int i = 0; i < 4; i++) {
            int k = g*4 + i;
            if (k < cnt) {
#pragma unroll
                for (int q = 0; q < 4; q++) {
                    int col = 2*tx + 16*q;
                    float l0, h0v, l1, h1v;
                    upk2(acc[i][2*q],   l0, h0v);
                    upk2(acc[i][2*q+1], l1, h1v);
                    pm[2*q]   = fmaxf(pm[2*q],   fmaxf(l0 + h0v + __ldg(&b3[h*64+col]),   0.f));
                    pm[2*q+1] = fmaxf(pm[2*q+1], fmaxf(l1 + h1v + __ldg(&b3[h*64+col+1]), 0.f));
                }
            }
        }
#pragma unroll
        for (int q = 0; q < 4; q++) {
            int col = 2*tx + 16*q;
            float2 v; v.x = pm[2*q]; v.y = pm[2*q+1];
            *(float2*)&red[((h*2 + ci)*16 + g)*64 + col] = v;
        }
    }
    __syncthreads();

    // ---- final reduce over the 16 row-groups, write output ----
    {
        int cci = tid >> 7, col = tid & 127;
        int h = col >> 6, c64 = col & 63;
        float mmv = -3.402823466e38f;
#pragma unroll
        for (int gg = 0; gg < 16; gg++)
            mmv = fmaxf(mmv, red[((h*2 + cci)*16 + gg)*64 + c64]);
        outF[(size_t)(m0+cci)*128 + col] = mmv;
    }
    if (tid < 2) outB[m0 + tid] = (float)((m0 + tid) >> 11);
}

// =========================================================================
extern "C" void kernel_launch(void* const* d_in, const int* in_sizes, int n_in,
                              void* d_out, int out_size)
{
    const float* pos = (const float*)d_in[0];
    const float* x   = (const float*)d_in[2];
    const float* W1  = (const float*)d_in[3];
    const float* b1  = (const float*)d_in[4];
    const float* W2  = (const float*)d_in[5];
    const float* b2  = (const float*)d_in[6];
    const float* W3  = (const float*)d_in[7];
    const float* b3  = (const float*)d_in[8];

    float* out      = (float*)d_out;
    float* out_cent = out;
    float* out_feat = out + (size_t)NC*3;
    float* out_b    = out + (size_t)NC*3 + (size_t)NC*128;

    const int mlp_smem = (2*128*66) * 4;   // 67584 B
    cudaFuncSetAttribute(fps_kernel, cudaFuncAttributeMaxDynamicSharedMemorySize, 3*PP*4);
    cudaFuncSetAttribute(mlp_kernel, cudaFuncAttributeMaxDynamicSharedMemorySize, mlp_smem);

    point_feat_kernel<<<(NPTS*64)/256, 256>>>(pos, x, W1, b1);
    wprep_kernel<<<32, 256>>>(W2, W3);
    fps_kernel<<<BB, 1024, 3*PP*4>>>(pos, out_cent);
    ball_kernel<<<(NC*32)/256, 256>>>(pos);
    mlp_kernel<<<NC/2, 256, mlp_smem>>>(W1, b2, b3, out_feat, out_b);
}